// round 14
// baseline (speedup 1.0000x reference)
#include <cuda_runtime.h>
#include <cuda_bf16.h>

#define N_NODES 50000
#define N_EDGES 1600000
#define OUT_H   (N_NODES * 96)
#define OUT_MU  OUT_H
#define OUT_MD  (OUT_H + N_EDGES)
#define NBLK_SCAN 49   // ceil(50000/1024)

// ---------------- scratch (device globals; no allocation allowed) ----------------
__device__ int   g_is64;
__device__ __align__(16) int   g_row[N_EDGES];
__device__ __align__(16) int   g_col[N_EDGES];
__device__ int   g_cnt_up[N_NODES];
__device__ int   g_cnt_dn[N_NODES];
__device__ int   g_off_up[N_NODES + 1];
__device__ int   g_off_dn[N_NODES + 1];
__device__ int   g_cur_up[N_NODES];
__device__ int   g_cur_dn[N_NODES];
__device__ int   g_part[2][64];
// CSR entries carry src + all 3 layers' edge weights: {src, w1, w2, w3} as int4.
__device__ __align__(16) int4  g_eup[N_EDGES];   // bucketed by col (up dst)
__device__ __align__(16) int4  g_edn[N_EDGES];   // bucketed by row (down dst)
__device__ __align__(16) float g_tmp_up[N_NODES * 32];
__device__ __align__(16) float g_tmp_down[N_NODES * 32];
__device__ __align__(16) float g_bias[N_NODES * 32];
__device__ __align__(16) float g_h[N_NODES * 96];

// ---------------- 0. zero counters + detect int64 vs int32 (block 0) ----------------
__global__ void k_zero_detect(const int* __restrict__ ei)
{
    int i = blockIdx.x * blockDim.x + threadIdx.x;
    if (i < N_NODES) { g_cnt_up[i] = 0; g_cnt_dn[i] = 0; }
    if (blockIdx.x == 0) {
        __shared__ int sh[256];
        int acc = 0;
        for (int k = threadIdx.x; k < 2048; k += 256)
            acc |= ei[2 * k + 1];
        sh[threadIdx.x] = acc;
        __syncthreads();
        for (int s = 128; s; s >>= 1) {
            if (threadIdx.x < s) sh[threadIdx.x] |= sh[threadIdx.x + s];
            __syncthreads();
        }
        if (threadIdx.x == 0) g_is64 = (sh[0] == 0) ? 1 : 0;
    }
}

// ---------------- 1. convert edge index + count degrees ----------------
__global__ void k_prep(const int* __restrict__ ei)
{
    int e = blockIdx.x * blockDim.x + threadIdx.x;
    if (e >= N_EDGES) return;
    int r, c;
    if (g_is64) {
        r = ei[2 * e];
        c = ei[2 * (N_EDGES + e)];
    } else {
        r = ei[e];
        c = ei[N_EDGES + e];
    }
    g_row[e] = r;
    g_col[e] = c;
    atomicAdd(&g_cnt_up[c], 1);
    atomicAdd(&g_cnt_dn[r], 1);
}

// ---------------- 2a. per-block inclusive scan ----------------
__global__ void k_blockscan()   // grid (NBLK_SCAN, 2), block 1024
{
    __shared__ int sh[1024];
    const int* cnt = blockIdx.y ? g_cnt_dn : g_cnt_up;
    int* off = blockIdx.y ? g_off_dn : g_off_up;
    int idx = blockIdx.x * 1024 + threadIdx.x;
    sh[threadIdx.x] = (idx < N_NODES) ? cnt[idx] : 0;
    __syncthreads();
#pragma unroll
    for (int ofs = 1; ofs < 1024; ofs <<= 1) {
        int t = (threadIdx.x >= ofs) ? sh[threadIdx.x - ofs] : 0;
        __syncthreads();
        sh[threadIdx.x] += t;
        __syncthreads();
    }
    if (idx < N_NODES) off[idx + 1] = sh[threadIdx.x];
    if (threadIdx.x == 1023) g_part[blockIdx.y][blockIdx.x] = sh[1023];
}

// ---------------- 2b. scan the block partials (2 warps, shfl scan) ----------------
__global__ void k_scanpart()
{
    int w = threadIdx.x >> 5, lane = threadIdx.x & 31;
    if (w >= 2) return;
    int* p = g_part[w];
    int carry = 0;
    for (int base = 0; base < NBLK_SCAN; base += 32) {
        int i = base + lane;
        int v = (i < NBLK_SCAN) ? p[i] : 0;
        int inc = v;
#pragma unroll
        for (int o = 1; o < 32; o <<= 1) {
            int t = __shfl_up_sync(0xFFFFFFFFu, inc, o);
            if (lane >= o) inc += t;
        }
        if (i < NBLK_SCAN) p[i] = carry + inc - v;   // exclusive
        carry += __shfl_sync(0xFFFFFFFFu, inc, 31);
    }
}

// ---------------- 2c. add carries + init fill cursors ----------------
__global__ void k_addcarry()    // grid (NBLK_SCAN, 2), block 1024
{
    int idx = blockIdx.x * 1024 + threadIdx.x;
    if (idx >= N_NODES) return;
    int* off = blockIdx.y ? g_off_dn : g_off_up;
    int* cur = blockIdx.y ? g_cur_dn : g_cur_up;
    int v = off[idx + 1] + g_part[blockIdx.y][blockIdx.x];
    off[idx + 1] = v;
    if (idx + 1 < N_NODES) cur[idx + 1] = v;
    if (idx == 0) { off[0] = 0; cur[0] = 0; }
}

// ---------------- 3. CSR fill (src + 3 layer weights packed) + means ----------------
__global__ void k_fillmean(const float* __restrict__ u1, const float* __restrict__ u2,
                           const float* __restrict__ u3, const float* __restrict__ d1,
                           const float* __restrict__ d2, const float* __restrict__ d3,
                           float* __restrict__ out)
{
    int e = blockIdx.x * blockDim.x + threadIdx.x;
    if (e >= N_EDGES) return;
    int r = g_row[e], c = g_col[e];
    float w1u = u1[e], w2u = u2[e], w3u = u3[e];
    float w1d = d1[e], w2d = d2[e], w3d = d3[e];

    int p = atomicAdd(&g_cur_up[c], 1);
    g_eup[p] = make_int4(r, __float_as_int(w1u), __float_as_int(w2u), __float_as_int(w3u));
    int q = atomicAdd(&g_cur_dn[r], 1);
    g_edn[q] = make_int4(c, __float_as_int(w1d), __float_as_int(w2d), __float_as_int(w3d));

    out[OUT_MU + e] = (w1u + w2u + w3u) / 3.0f;
    out[OUT_MD + e] = (w1d + w2d + w3d) / 3.0f;
}

// ---------------- 4. fused 3-matrix GEMM, 2 nodes per thread ----------------
template <int DIN, int DP>
__global__ void k_gemm(const float* __restrict__ xin, int hsel,
                       const float* __restrict__ wu, const float* __restrict__ wd,
                       const float* __restrict__ wb)
{
    __shared__ float Wsh[96 * DP];
    __shared__ float hsh[16 * DIN];
    const float* h = hsel ? (const float*)g_h : xin;

    int tid = threadIdx.x;
    for (int idx = tid; idx < 96 * DIN; idx += 256) {
        int m = idx / DIN, k = idx % DIN;
        const float* W = (m < 32) ? wu : (m < 64 ? wd : wb);
        Wsh[m * DP + k] = W[(m & 31) * DIN + k];
    }
    __syncthreads();

    int i = tid >> 5;
    int j = tid & 31;
    int n0 = blockIdx.x * 128;
    const float4* A = (const float4*)&Wsh[j * DP];
    const float4* B = (const float4*)&Wsh[(j + 32) * DP];
    const float4* C = (const float4*)&Wsh[(j + 64) * DP];

    for (int it = 0; it < 8; it++) {
        int nb = n0 + it * 16;
        for (int idx = tid; idx < 16 * DIN; idx += 256) {
            int node = nb + idx / DIN;
            hsh[idx] = (node < N_NODES) ? h[node * DIN + idx % DIN] : 0.f;
        }
        __syncthreads();

        float au0 = 0.f, ad0 = 0.f, ab0 = 0.f;
        float au1 = 0.f, ad1 = 0.f, ab1 = 0.f;
        const float4* H0 = (const float4*)&hsh[(2 * i) * DIN];
        const float4* H1 = (const float4*)&hsh[(2 * i + 1) * DIN];
#pragma unroll
        for (int k4 = 0; k4 < DIN / 4; k4++) {
            float4 a = A[k4], b = B[k4], c = C[k4];
            float4 h0 = H0[k4], h1 = H1[k4];
            au0 = fmaf(h0.x, a.x, fmaf(h0.y, a.y, fmaf(h0.z, a.z, fmaf(h0.w, a.w, au0))));
            ad0 = fmaf(h0.x, b.x, fmaf(h0.y, b.y, fmaf(h0.z, b.z, fmaf(h0.w, b.w, ad0))));
            ab0 = fmaf(h0.x, c.x, fmaf(h0.y, c.y, fmaf(h0.z, c.z, fmaf(h0.w, c.w, ab0))));
            au1 = fmaf(h1.x, a.x, fmaf(h1.y, a.y, fmaf(h1.z, a.z, fmaf(h1.w, a.w, au1))));
            ad1 = fmaf(h1.x, b.x, fmaf(h1.y, b.y, fmaf(h1.z, b.z, fmaf(h1.w, b.w, ad1))));
            ab1 = fmaf(h1.x, c.x, fmaf(h1.y, c.y, fmaf(h1.z, c.z, fmaf(h1.w, c.w, ab1))));
        }
        int na = nb + 2 * i, nbb = na + 1;
        if (na < N_NODES) {
            g_tmp_up[na * 32 + j]   = au0;
            g_tmp_down[na * 32 + j] = ad0;
            g_bias[na * 32 + j]     = ab0;
        }
        if (nbb < N_NODES) {
            g_tmp_up[nbb * 32 + j]   = au1;
            g_tmp_down[nbb * 32 + j] = ad1;
            g_bias[nbb * 32 + j]     = ab1;
        }
        __syncthreads();
    }
}

// ---------------- 5. fused propagate(up+down) + norm + leaky ----------------
// One warp per node, lane = feature column. Each edge batch: one coalesced
// int4 load per lane (src + weight for this layer, no eid gather), staged to
// shared; consumption unrolled x4 with 4 accumulators for LDG MLP.
template <int L>
__device__ __forceinline__ float seg_sum(const int* __restrict__ off,
                                         const int4* __restrict__ csr,
                                         const float* __restrict__ tmp,
                                         int n, int lane, int2* __restrict__ stg)
{
    int s0 = off[n], s1 = off[n + 1];
    float acc0 = 0.f, acc1 = 0.f, acc2 = 0.f, acc3 = 0.f;
    for (int base = s0; base < s1; base += 32) {
        int idx = base + lane;
        if (idx < s1) {
            int4 ent = csr[idx];
            int w = (L == 0) ? ent.y : (L == 1) ? ent.z : ent.w;
            stg[lane] = make_int2(ent.x, w);
        }
        __syncwarp();
        int cnt = min(32, s1 - base);
        int t = 0;
        for (; t + 4 <= cnt; t += 4) {
            int2 e0 = stg[t], e1 = stg[t + 1], e2 = stg[t + 2], e3 = stg[t + 3];
            float v0 = tmp[e0.x * 32 + lane];
            float v1 = tmp[e1.x * 32 + lane];
            float v2 = tmp[e2.x * 32 + lane];
            float v3 = tmp[e3.x * 32 + lane];
            acc0 = fmaf(__int_as_float(e0.y), v0, acc0);
            acc1 = fmaf(__int_as_float(e1.y), v1, acc1);
            acc2 = fmaf(__int_as_float(e2.y), v2, acc2);
            acc3 = fmaf(__int_as_float(e3.y), v3, acc3);
        }
        for (; t < cnt; t++) {
            int2 e0 = stg[t];
            acc0 = fmaf(__int_as_float(e0.y), tmp[e0.x * 32 + lane], acc0);
        }
        __syncwarp();
    }
    int deg = s1 - s0;
    float acc = (acc0 + acc1) + (acc2 + acc3);
    return deg > 0 ? acc * (1.0f / (float)deg) : 0.f;
}

template <int L>
__global__ void k_prop_norm(float* __restrict__ out, int toOut)
{
    __shared__ int2 stage[8][32];
    int gt = blockIdx.x * blockDim.x + threadIdx.x;
    int n = gt >> 5;
    int lane = gt & 31;
    int wid = (threadIdx.x >> 5);
    if (n >= N_NODES) return;

    float up = seg_sum<L>(g_off_up, g_eup, g_tmp_up,   n, lane, stage[wid]);
    float dn = seg_sum<L>(g_off_dn, g_edn, g_tmp_down, n, lane, stage[wid]);
    float b  = g_bias[n * 32 + lane];

    float ss = up * up + dn * dn + b * b;
#pragma unroll
    for (int o = 16; o; o >>= 1) ss += __shfl_xor_sync(0xFFFFFFFFu, ss, o);
    float inv = 1.0f / fmaxf(sqrtf(ss), 1e-12f);

    float va = up * inv; va = va >= 0.f ? va : 0.1f * va;
    float vb = dn * inv; vb = vb >= 0.f ? vb : 0.1f * vb;
    float vc = b  * inv; vc = vc >= 0.f ? vc : 0.1f * vc;

    float* dstp = toOut ? out : (float*)g_h;
    dstp[n * 96 + lane]      = va;
    dstp[n * 96 + 32 + lane] = vb;
    dstp[n * 96 + 64 + lane] = vc;
}

// ---------------- host launch ----------------
extern "C" void kernel_launch(void* const* d_in, const int* in_sizes, int n_in,
                              void* d_out, int out_size)
{
    const float* x   = (const float*)d_in[0];
    const int*   ei  = (const int*)d_in[1];
    const float* w1u = (const float*)d_in[2];
    const float* w1d = (const float*)d_in[3];
    const float* w1b = (const float*)d_in[4];
    const float* e1u = (const float*)d_in[5];
    const float* e1d = (const float*)d_in[6];
    const float* w2u = (const float*)d_in[7];
    const float* w2d = (const float*)d_in[8];
    const float* w2b = (const float*)d_in[9];
    const float* e2u = (const float*)d_in[10];
    const float* e2d = (const float*)d_in[11];
    const float* w3u = (const float*)d_in[12];
    const float* w3d = (const float*)d_in[13];
    const float* w3b = (const float*)d_in[14];
    const float* e3u = (const float*)d_in[15];
    const float* e3d = (const float*)d_in[16];
    float* out = (float*)d_out;

    const int NB_N    = (N_NODES + 255) / 256;             // 196
    const int NB_E    = N_EDGES / 256;                     // 6250
    const int NB_GEMM = (N_NODES + 127) / 128;             // 391
    const int NB_PROP = (N_NODES * 32 + 255) / 256;        // 6250
    dim3 scan_grid(NBLK_SCAN, 2);

    // ---- prep + CSR build ----
    k_zero_detect<<<NB_N, 256>>>(ei);
    k_prep<<<NB_E, 256>>>(ei);
    k_blockscan<<<scan_grid, 1024>>>();
    k_scanpart<<<1, 64>>>();
    k_addcarry<<<scan_grid, 1024>>>();
    k_fillmean<<<NB_E, 256>>>(e1u, e2u, e3u, e1d, e2d, e3d, out);

    // ---- layer 1 ----
    k_gemm<8, 12><<<NB_GEMM, 256>>>(x, 0, w1u, w1d, w1b);
    k_prop_norm<0><<<NB_PROP, 256>>>(nullptr, 0);

    // ---- layer 2 ----
    k_gemm<96, 100><<<NB_GEMM, 256>>>(nullptr, 1, w2u, w2d, w2b);
    k_prop_norm<1><<<NB_PROP, 256>>>(nullptr, 0);

    // ---- layer 3 ----
    k_gemm<96, 100><<<NB_GEMM, 256>>>(nullptr, 1, w3u, w3d, w3b);
    k_prop_norm<2><<<NB_PROP, 256>>>(out, 1);
}

// round 15
// speedup vs baseline: 1.0090x; 1.0090x over previous
#include <cuda_runtime.h>
#include <cuda_bf16.h>

#define N_NODES 50000
#define N_EDGES 1600000
#define OUT_H   (N_NODES * 96)
#define OUT_MU  OUT_H
#define OUT_MD  (OUT_H + N_EDGES)
#define NBLK_SCAN 49   // ceil(50000/1024)

// ---------------- scratch (device globals; no allocation allowed) ----------------
__device__ int   g_is64;
__device__ __align__(16) int   g_row[N_EDGES];
__device__ __align__(16) int   g_col[N_EDGES];
__device__ int   g_cnt_up[N_NODES];
__device__ int   g_cnt_dn[N_NODES];
__device__ int   g_off_up[N_NODES + 1];
__device__ int   g_off_dn[N_NODES + 1];
__device__ int   g_cur_up[N_NODES];
__device__ int   g_cur_dn[N_NODES];
__device__ int   g_part[2][64];
// CSR entries carry src + all 3 layers' edge weights: {src, w1, w2, w3} as int4.
__device__ __align__(16) int4  g_eup[N_EDGES];   // bucketed by col (up dst)
__device__ __align__(16) int4  g_edn[N_EDGES];   // bucketed by row (down dst)
__device__ __align__(16) float g_tmp_up[N_NODES * 32];
__device__ __align__(16) float g_tmp_down[N_NODES * 32];
__device__ __align__(16) float g_bias[N_NODES * 32];
__device__ __align__(16) float g_h[N_NODES * 96];

// ---------------- 0. zero counters + detect int64 vs int32 (block 0) ----------------
__global__ void k_zero_detect(const int* __restrict__ ei)
{
    int i = blockIdx.x * blockDim.x + threadIdx.x;
    if (i < N_NODES) { g_cnt_up[i] = 0; g_cnt_dn[i] = 0; }
    if (blockIdx.x == 0) {
        __shared__ int sh[256];
        int acc = 0;
        for (int k = threadIdx.x; k < 2048; k += 256)
            acc |= ei[2 * k + 1];
        sh[threadIdx.x] = acc;
        __syncthreads();
        for (int s = 128; s; s >>= 1) {
            if (threadIdx.x < s) sh[threadIdx.x] |= sh[threadIdx.x + s];
            __syncthreads();
        }
        if (threadIdx.x == 0) g_is64 = (sh[0] == 0) ? 1 : 0;
    }
}

// ---------------- 1. convert edge index + count degrees ----------------
__global__ void k_prep(const int* __restrict__ ei)
{
    int e = blockIdx.x * blockDim.x + threadIdx.x;
    if (e >= N_EDGES) return;
    int r, c;
    if (g_is64) {
        r = ei[2 * e];
        c = ei[2 * (N_EDGES + e)];
    } else {
        r = ei[e];
        c = ei[N_EDGES + e];
    }
    g_row[e] = r;
    g_col[e] = c;
    atomicAdd(&g_cnt_up[c], 1);
    atomicAdd(&g_cnt_dn[r], 1);
}

// ---------------- 2a. per-block inclusive scan ----------------
__global__ void k_blockscan()   // grid (NBLK_SCAN, 2), block 1024
{
    __shared__ int sh[1024];
    const int* cnt = blockIdx.y ? g_cnt_dn : g_cnt_up;
    int* off = blockIdx.y ? g_off_dn : g_off_up;
    int idx = blockIdx.x * 1024 + threadIdx.x;
    sh[threadIdx.x] = (idx < N_NODES) ? cnt[idx] : 0;
    __syncthreads();
#pragma unroll
    for (int ofs = 1; ofs < 1024; ofs <<= 1) {
        int t = (threadIdx.x >= ofs) ? sh[threadIdx.x - ofs] : 0;
        __syncthreads();
        sh[threadIdx.x] += t;
        __syncthreads();
    }
    if (idx < N_NODES) off[idx + 1] = sh[threadIdx.x];
    if (threadIdx.x == 1023) g_part[blockIdx.y][blockIdx.x] = sh[1023];
}

// ---------------- 2b. scan the block partials (2 warps, shfl scan) ----------------
__global__ void k_scanpart()
{
    int w = threadIdx.x >> 5, lane = threadIdx.x & 31;
    if (w >= 2) return;
    int* p = g_part[w];
    int carry = 0;
    for (int base = 0; base < NBLK_SCAN; base += 32) {
        int i = base + lane;
        int v = (i < NBLK_SCAN) ? p[i] : 0;
        int inc = v;
#pragma unroll
        for (int o = 1; o < 32; o <<= 1) {
            int t = __shfl_up_sync(0xFFFFFFFFu, inc, o);
            if (lane >= o) inc += t;
        }
        if (i < NBLK_SCAN) p[i] = carry + inc - v;   // exclusive
        carry += __shfl_sync(0xFFFFFFFFu, inc, 31);
    }
}

// ---------------- 2c. add carries + init fill cursors ----------------
__global__ void k_addcarry()    // grid (NBLK_SCAN, 2), block 1024
{
    int idx = blockIdx.x * 1024 + threadIdx.x;
    if (idx >= N_NODES) return;
    int* off = blockIdx.y ? g_off_dn : g_off_up;
    int* cur = blockIdx.y ? g_cur_dn : g_cur_up;
    int v = off[idx + 1] + g_part[blockIdx.y][blockIdx.x];
    off[idx + 1] = v;
    if (idx + 1 < N_NODES) cur[idx + 1] = v;
    if (idx == 0) { off[0] = 0; cur[0] = 0; }
}

// ---------------- 3. CSR fill (src + 3 layer weights packed) + means ----------------
__global__ void k_fillmean(const float* __restrict__ u1, const float* __restrict__ u2,
                           const float* __restrict__ u3, const float* __restrict__ d1,
                           const float* __restrict__ d2, const float* __restrict__ d3,
                           float* __restrict__ out)
{
    int e = blockIdx.x * blockDim.x + threadIdx.x;
    if (e >= N_EDGES) return;
    int r = g_row[e], c = g_col[e];
    float w1u = u1[e], w2u = u2[e], w3u = u3[e];
    float w1d = d1[e], w2d = d2[e], w3d = d3[e];

    int p = atomicAdd(&g_cur_up[c], 1);
    g_eup[p] = make_int4(r, __float_as_int(w1u), __float_as_int(w2u), __float_as_int(w3u));
    int q = atomicAdd(&g_cur_dn[r], 1);
    g_edn[q] = make_int4(c, __float_as_int(w1d), __float_as_int(w2d), __float_as_int(w3d));

    out[OUT_MU + e] = (w1u + w2u + w3u) / 3.0f;
    out[OUT_MD + e] = (w1d + w2d + w3d) / 3.0f;
}

// ---------------- 4. fused 3-matrix GEMM, 2 nodes per thread ----------------
template <int DIN, int DP>
__global__ void k_gemm(const float* __restrict__ xin, int hsel,
                       const float* __restrict__ wu, const float* __restrict__ wd,
                       const float* __restrict__ wb)
{
    __shared__ float Wsh[96 * DP];
    __shared__ float hsh[16 * DIN];
    const float* h = hsel ? (const float*)g_h : xin;

    int tid = threadIdx.x;
    for (int idx = tid; idx < 96 * DIN; idx += 256) {
        int m = idx / DIN, k = idx % DIN;
        const float* W = (m < 32) ? wu : (m < 64 ? wd : wb);
        Wsh[m * DP + k] = W[(m & 31) * DIN + k];
    }
    __syncthreads();

    int i = tid >> 5;
    int j = tid & 31;
    int n0 = blockIdx.x * 128;
    const float4* A = (const float4*)&Wsh[j * DP];
    const float4* B = (const float4*)&Wsh[(j + 32) * DP];
    const float4* C = (const float4*)&Wsh[(j + 64) * DP];

    for (int it = 0; it < 8; it++) {
        int nb = n0 + it * 16;
        for (int idx = tid; idx < 16 * DIN; idx += 256) {
            int node = nb + idx / DIN;
            hsh[idx] = (node < N_NODES) ? h[node * DIN + idx % DIN] : 0.f;
        }
        __syncthreads();

        float au0 = 0.f, ad0 = 0.f, ab0 = 0.f;
        float au1 = 0.f, ad1 = 0.f, ab1 = 0.f;
        const float4* H0 = (const float4*)&hsh[(2 * i) * DIN];
        const float4* H1 = (const float4*)&hsh[(2 * i + 1) * DIN];
#pragma unroll
        for (int k4 = 0; k4 < DIN / 4; k4++) {
            float4 a = A[k4], b = B[k4], c = C[k4];
            float4 h0 = H0[k4], h1 = H1[k4];
            au0 = fmaf(h0.x, a.x, fmaf(h0.y, a.y, fmaf(h0.z, a.z, fmaf(h0.w, a.w, au0))));
            ad0 = fmaf(h0.x, b.x, fmaf(h0.y, b.y, fmaf(h0.z, b.z, fmaf(h0.w, b.w, ad0))));
            ab0 = fmaf(h0.x, c.x, fmaf(h0.y, c.y, fmaf(h0.z, c.z, fmaf(h0.w, c.w, ab0))));
            au1 = fmaf(h1.x, a.x, fmaf(h1.y, a.y, fmaf(h1.z, a.z, fmaf(h1.w, a.w, au1))));
            ad1 = fmaf(h1.x, b.x, fmaf(h1.y, b.y, fmaf(h1.z, b.z, fmaf(h1.w, b.w, ad1))));
            ab1 = fmaf(h1.x, c.x, fmaf(h1.y, c.y, fmaf(h1.z, c.z, fmaf(h1.w, c.w, ab1))));
        }
        int na = nb + 2 * i, nbb = na + 1;
        if (na < N_NODES) {
            g_tmp_up[na * 32 + j]   = au0;
            g_tmp_down[na * 32 + j] = ad0;
            g_bias[na * 32 + j]     = ab0;
        }
        if (nbb < N_NODES) {
            g_tmp_up[nbb * 32 + j]   = au1;
            g_tmp_down[nbb * 32 + j] = ad1;
            g_bias[nbb * 32 + j]     = ab1;
        }
        __syncthreads();
    }
}

// ---------------- 5. fused propagate(up+down) + norm + leaky ----------------
// One warp per node, lane = feature column. Each edge batch: one coalesced
// int4 load per lane (src + weight for this layer, no eid gather), staged to
// shared; consumption unrolled x4 with 4 accumulators for LDG MLP.
template <int L>
__device__ __forceinline__ float seg_sum(const int* __restrict__ off,
                                         const int4* __restrict__ csr,
                                         const float* __restrict__ tmp,
                                         int n, int lane, int2* __restrict__ stg)
{
    int s0 = off[n], s1 = off[n + 1];
    float acc0 = 0.f, acc1 = 0.f, acc2 = 0.f, acc3 = 0.f;
    for (int base = s0; base < s1; base += 32) {
        int idx = base + lane;
        if (idx < s1) {
            int4 ent = csr[idx];
            int w = (L == 0) ? ent.y : (L == 1) ? ent.z : ent.w;
            stg[lane] = make_int2(ent.x, w);
        }
        __syncwarp();
        int cnt = min(32, s1 - base);
        int t = 0;
        for (; t + 4 <= cnt; t += 4) {
            int2 e0 = stg[t], e1 = stg[t + 1], e2 = stg[t + 2], e3 = stg[t + 3];
            float v0 = tmp[e0.x * 32 + lane];
            float v1 = tmp[e1.x * 32 + lane];
            float v2 = tmp[e2.x * 32 + lane];
            float v3 = tmp[e3.x * 32 + lane];
            acc0 = fmaf(__int_as_float(e0.y), v0, acc0);
            acc1 = fmaf(__int_as_float(e1.y), v1, acc1);
            acc2 = fmaf(__int_as_float(e2.y), v2, acc2);
            acc3 = fmaf(__int_as_float(e3.y), v3, acc3);
        }
        for (; t < cnt; t++) {
            int2 e0 = stg[t];
            acc0 = fmaf(__int_as_float(e0.y), tmp[e0.x * 32 + lane], acc0);
        }
        __syncwarp();
    }
    int deg = s1 - s0;
    float acc = (acc0 + acc1) + (acc2 + acc3);
    return deg > 0 ? acc * (1.0f / (float)deg) : 0.f;
}

template <int L>
__global__ void k_prop_norm(float* __restrict__ out, int toOut)
{
    __shared__ int2 stage[8][32];
    int gt = blockIdx.x * blockDim.x + threadIdx.x;
    int n = gt >> 5;
    int lane = gt & 31;
    int wid = (threadIdx.x >> 5);
    if (n >= N_NODES) return;

    float up = seg_sum<L>(g_off_up, g_eup, g_tmp_up,   n, lane, stage[wid]);
    float dn = seg_sum<L>(g_off_dn, g_edn, g_tmp_down, n, lane, stage[wid]);
    float b  = g_bias[n * 32 + lane];

    float ss = up * up + dn * dn + b * b;
#pragma unroll
    for (int o = 16; o; o >>= 1) ss += __shfl_xor_sync(0xFFFFFFFFu, ss, o);
    float inv = 1.0f / fmaxf(sqrtf(ss), 1e-12f);

    float va = up * inv; va = va >= 0.f ? va : 0.1f * va;
    float vb = dn * inv; vb = vb >= 0.f ? vb : 0.1f * vb;
    float vc = b  * inv; vc = vc >= 0.f ? vc : 0.1f * vc;

    float* dstp = toOut ? out : (float*)g_h;
    dstp[n * 96 + lane]      = va;
    dstp[n * 96 + 32 + lane] = vb;
    dstp[n * 96 + 64 + lane] = vc;
}

// ---------------- host launch ----------------
extern "C" void kernel_launch(void* const* d_in, const int* in_sizes, int n_in,
                              void* d_out, int out_size)
{
    const float* x   = (const float*)d_in[0];
    const int*   ei  = (const int*)d_in[1];
    const float* w1u = (const float*)d_in[2];
    const float* w1d = (const float*)d_in[3];
    const float* w1b = (const float*)d_in[4];
    const float* e1u = (const float*)d_in[5];
    const float* e1d = (const float*)d_in[6];
    const float* w2u = (const float*)d_in[7];
    const float* w2d = (const float*)d_in[8];
    const float* w2b = (const float*)d_in[9];
    const float* e2u = (const float*)d_in[10];
    const float* e2d = (const float*)d_in[11];
    const float* w3u = (const float*)d_in[12];
    const float* w3d = (const float*)d_in[13];
    const float* w3b = (const float*)d_in[14];
    const float* e3u = (const float*)d_in[15];
    const float* e3d = (const float*)d_in[16];
    float* out = (float*)d_out;

    const int NB_N    = (N_NODES + 255) / 256;             // 196
    const int NB_E    = N_EDGES / 256;                     // 6250
    const int NB_GEMM = (N_NODES + 127) / 128;             // 391
    const int NB_PROP = (N_NODES * 32 + 255) / 256;        // 6250
    dim3 scan_grid(NBLK_SCAN, 2);

    // ---- prep + CSR build ----
    k_zero_detect<<<NB_N, 256>>>(ei);
    k_prep<<<NB_E, 256>>>(ei);
    k_blockscan<<<scan_grid, 1024>>>();
    k_scanpart<<<1, 64>>>();
    k_addcarry<<<scan_grid, 1024>>>();
    k_fillmean<<<NB_E, 256>>>(e1u, e2u, e3u, e1d, e2d, e3d, out);

    // ---- layer 1 ----
    k_gemm<8, 12><<<NB_GEMM, 256>>>(x, 0, w1u, w1d, w1b);
    k_prop_norm<0><<<NB_PROP, 256>>>(nullptr, 0);

    // ---- layer 2 ----
    k_gemm<96, 100><<<NB_GEMM, 256>>>(nullptr, 1, w2u, w2d, w2b);
    k_prop_norm<1><<<NB_PROP, 256>>>(nullptr, 0);

    // ---- layer 3 ----
    k_gemm<96, 100><<<NB_GEMM, 256>>>(nullptr, 1, w3u, w3d, w3b);
    k_prop_norm<2><<<NB_PROP, 256>>>(out, 1);
}

// round 16
// speedup vs baseline: 1.0110x; 1.0020x over previous
#include <cuda_runtime.h>
#include <cuda_bf16.h>

#define N_NODES 50000
#define N_EDGES 1600000
#define OUT_H   (N_NODES * 96)
#define OUT_MU  OUT_H
#define OUT_MD  (OUT_H + N_EDGES)
#define NBLK_SCAN 49   // ceil(50000/1024)

// ---------------- scratch (device globals; no allocation allowed) ----------------
__device__ int   g_is64;
__device__ __align__(16) int   g_row[N_EDGES];
__device__ __align__(16) int   g_col[N_EDGES];
__device__ int   g_cnt_up[N_NODES];
__device__ int   g_cnt_dn[N_NODES];
__device__ int   g_off_up[N_NODES + 1];
__device__ int   g_off_dn[N_NODES + 1];
__device__ int   g_cur_up[N_NODES];
__device__ int   g_cur_dn[N_NODES];
__device__ int   g_part[2][64];
// CSR entries carry src + all 3 layers' edge weights: {src, w1, w2, w3} as int4.
__device__ __align__(16) int4  g_eup[N_EDGES];   // bucketed by col (up dst)
__device__ __align__(16) int4  g_edn[N_EDGES];   // bucketed by row (down dst)
__device__ __align__(16) float g_tmp_up[N_NODES * 32];
__device__ __align__(16) float g_tmp_down[N_NODES * 32];
__device__ __align__(16) float g_bias[N_NODES * 32];
__device__ __align__(16) float g_h[N_NODES * 96];

// ---------------- 0. zero counters + detect int64 vs int32 (block 0) ----------------
__global__ void k_zero_detect(const int* __restrict__ ei)
{
    int i = blockIdx.x * blockDim.x + threadIdx.x;
    if (i < N_NODES) { g_cnt_up[i] = 0; g_cnt_dn[i] = 0; }
    if (blockIdx.x == 0) {
        __shared__ int sh[256];
        int acc = 0;
        for (int k = threadIdx.x; k < 2048; k += 256)
            acc |= ei[2 * k + 1];
        sh[threadIdx.x] = acc;
        __syncthreads();
        for (int s = 128; s; s >>= 1) {
            if (threadIdx.x < s) sh[threadIdx.x] |= sh[threadIdx.x + s];
            __syncthreads();
        }
        if (threadIdx.x == 0) g_is64 = (sh[0] == 0) ? 1 : 0;
    }
}

// ---------------- 1. convert edge index + count degrees ----------------
__global__ void k_prep(const int* __restrict__ ei)
{
    int e = blockIdx.x * blockDim.x + threadIdx.x;
    if (e >= N_EDGES) return;
    int r, c;
    if (g_is64) {
        r = ei[2 * e];
        c = ei[2 * (N_EDGES + e)];
    } else {
        r = ei[e];
        c = ei[N_EDGES + e];
    }
    g_row[e] = r;
    g_col[e] = c;
    atomicAdd(&g_cnt_up[c], 1);
    atomicAdd(&g_cnt_dn[r], 1);
}

// ---------------- 2a. per-block inclusive scan ----------------
__global__ void k_blockscan()   // grid (NBLK_SCAN, 2), block 1024
{
    __shared__ int sh[1024];
    const int* cnt = blockIdx.y ? g_cnt_dn : g_cnt_up;
    int* off = blockIdx.y ? g_off_dn : g_off_up;
    int idx = blockIdx.x * 1024 + threadIdx.x;
    sh[threadIdx.x] = (idx < N_NODES) ? cnt[idx] : 0;
    __syncthreads();
#pragma unroll
    for (int ofs = 1; ofs < 1024; ofs <<= 1) {
        int t = (threadIdx.x >= ofs) ? sh[threadIdx.x - ofs] : 0;
        __syncthreads();
        sh[threadIdx.x] += t;
        __syncthreads();
    }
    if (idx < N_NODES) off[idx + 1] = sh[threadIdx.x];
    if (threadIdx.x == 1023) g_part[blockIdx.y][blockIdx.x] = sh[1023];
}

// ---------------- 2b. scan the block partials (2 warps, shfl scan) ----------------
__global__ void k_scanpart()
{
    int w = threadIdx.x >> 5, lane = threadIdx.x & 31;
    if (w >= 2) return;
    int* p = g_part[w];
    int carry = 0;
    for (int base = 0; base < NBLK_SCAN; base += 32) {
        int i = base + lane;
        int v = (i < NBLK_SCAN) ? p[i] : 0;
        int inc = v;
#pragma unroll
        for (int o = 1; o < 32; o <<= 1) {
            int t = __shfl_up_sync(0xFFFFFFFFu, inc, o);
            if (lane >= o) inc += t;
        }
        if (i < NBLK_SCAN) p[i] = carry + inc - v;   // exclusive
        carry += __shfl_sync(0xFFFFFFFFu, inc, 31);
    }
}

// ---------------- 2c. add carries + init fill cursors ----------------
__global__ void k_addcarry()    // grid (NBLK_SCAN, 2), block 1024
{
    int idx = blockIdx.x * 1024 + threadIdx.x;
    if (idx >= N_NODES) return;
    int* off = blockIdx.y ? g_off_dn : g_off_up;
    int* cur = blockIdx.y ? g_cur_dn : g_cur_up;
    int v = off[idx + 1] + g_part[blockIdx.y][blockIdx.x];
    off[idx + 1] = v;
    if (idx + 1 < N_NODES) cur[idx + 1] = v;
    if (idx == 0) { off[0] = 0; cur[0] = 0; }
}

// ---------------- 3. CSR fill (src + 3 layer weights packed) + means ----------------
__global__ void k_fillmean(const float* __restrict__ u1, const float* __restrict__ u2,
                           const float* __restrict__ u3, const float* __restrict__ d1,
                           const float* __restrict__ d2, const float* __restrict__ d3,
                           float* __restrict__ out)
{
    int e = blockIdx.x * blockDim.x + threadIdx.x;
    if (e >= N_EDGES) return;
    int r = g_row[e], c = g_col[e];
    float w1u = u1[e], w2u = u2[e], w3u = u3[e];
    float w1d = d1[e], w2d = d2[e], w3d = d3[e];

    int p = atomicAdd(&g_cur_up[c], 1);
    g_eup[p] = make_int4(r, __float_as_int(w1u), __float_as_int(w2u), __float_as_int(w3u));
    int q = atomicAdd(&g_cur_dn[r], 1);
    g_edn[q] = make_int4(c, __float_as_int(w1d), __float_as_int(w2d), __float_as_int(w3d));

    out[OUT_MU + e] = (w1u + w2u + w3u) / 3.0f;
    out[OUT_MD + e] = (w1d + w2d + w3d) / 3.0f;
}

// ---------------- 4. fused 3-matrix GEMM, 2 nodes per thread ----------------
template <int DIN, int DP>
__global__ void k_gemm(const float* __restrict__ xin, int hsel,
                       const float* __restrict__ wu, const float* __restrict__ wd,
                       const float* __restrict__ wb)
{
    __shared__ float Wsh[96 * DP];
    __shared__ float hsh[16 * DIN];
    const float* h = hsel ? (const float*)g_h : xin;

    int tid = threadIdx.x;
    for (int idx = tid; idx < 96 * DIN; idx += 256) {
        int m = idx / DIN, k = idx % DIN;
        const float* W = (m < 32) ? wu : (m < 64 ? wd : wb);
        Wsh[m * DP + k] = W[(m & 31) * DIN + k];
    }
    __syncthreads();

    int i = tid >> 5;
    int j = tid & 31;
    int n0 = blockIdx.x * 128;
    const float4* A = (const float4*)&Wsh[j * DP];
    const float4* B = (const float4*)&Wsh[(j + 32) * DP];
    const float4* C = (const float4*)&Wsh[(j + 64) * DP];

    for (int it = 0; it < 8; it++) {
        int nb = n0 + it * 16;
        for (int idx = tid; idx < 16 * DIN; idx += 256) {
            int node = nb + idx / DIN;
            hsh[idx] = (node < N_NODES) ? h[node * DIN + idx % DIN] : 0.f;
        }
        __syncthreads();

        float au0 = 0.f, ad0 = 0.f, ab0 = 0.f;
        float au1 = 0.f, ad1 = 0.f, ab1 = 0.f;
        const float4* H0 = (const float4*)&hsh[(2 * i) * DIN];
        const float4* H1 = (const float4*)&hsh[(2 * i + 1) * DIN];
#pragma unroll
        for (int k4 = 0; k4 < DIN / 4; k4++) {
            float4 a = A[k4], b = B[k4], c = C[k4];
            float4 h0 = H0[k4], h1 = H1[k4];
            au0 = fmaf(h0.x, a.x, fmaf(h0.y, a.y, fmaf(h0.z, a.z, fmaf(h0.w, a.w, au0))));
            ad0 = fmaf(h0.x, b.x, fmaf(h0.y, b.y, fmaf(h0.z, b.z, fmaf(h0.w, b.w, ad0))));
            ab0 = fmaf(h0.x, c.x, fmaf(h0.y, c.y, fmaf(h0.z, c.z, fmaf(h0.w, c.w, ab0))));
            au1 = fmaf(h1.x, a.x, fmaf(h1.y, a.y, fmaf(h1.z, a.z, fmaf(h1.w, a.w, au1))));
            ad1 = fmaf(h1.x, b.x, fmaf(h1.y, b.y, fmaf(h1.z, b.z, fmaf(h1.w, b.w, ad1))));
            ab1 = fmaf(h1.x, c.x, fmaf(h1.y, c.y, fmaf(h1.z, c.z, fmaf(h1.w, c.w, ab1))));
        }
        int na = nb + 2 * i, nbb = na + 1;
        if (na < N_NODES) {
            g_tmp_up[na * 32 + j]   = au0;
            g_tmp_down[na * 32 + j] = ad0;
            g_bias[na * 32 + j]     = ab0;
        }
        if (nbb < N_NODES) {
            g_tmp_up[nbb * 32 + j]   = au1;
            g_tmp_down[nbb * 32 + j] = ad1;
            g_bias[nbb * 32 + j]     = ab1;
        }
        __syncthreads();
    }
}

// ---------------- 5. fused propagate(up+down) + norm + leaky ----------------
// One warp per node, lane = feature column. Each edge batch: one coalesced
// int4 load per lane (src + weight for this layer, no eid gather), staged to
// shared; consumption unrolled x4 with 4 accumulators for LDG MLP.
template <int L>
__device__ __forceinline__ float seg_sum(const int* __restrict__ off,
                                         const int4* __restrict__ csr,
                                         const float* __restrict__ tmp,
                                         int n, int lane, int2* __restrict__ stg)
{
    int s0 = off[n], s1 = off[n + 1];
    float acc0 = 0.f, acc1 = 0.f, acc2 = 0.f, acc3 = 0.f;
    for (int base = s0; base < s1; base += 32) {
        int idx = base + lane;
        if (idx < s1) {
            int4 ent = csr[idx];
            int w = (L == 0) ? ent.y : (L == 1) ? ent.z : ent.w;
            stg[lane] = make_int2(ent.x, w);
        }
        __syncwarp();
        int cnt = min(32, s1 - base);
        int t = 0;
        for (; t + 4 <= cnt; t += 4) {
            int2 e0 = stg[t], e1 = stg[t + 1], e2 = stg[t + 2], e3 = stg[t + 3];
            float v0 = tmp[e0.x * 32 + lane];
            float v1 = tmp[e1.x * 32 + lane];
            float v2 = tmp[e2.x * 32 + lane];
            float v3 = tmp[e3.x * 32 + lane];
            acc0 = fmaf(__int_as_float(e0.y), v0, acc0);
            acc1 = fmaf(__int_as_float(e1.y), v1, acc1);
            acc2 = fmaf(__int_as_float(e2.y), v2, acc2);
            acc3 = fmaf(__int_as_float(e3.y), v3, acc3);
        }
        for (; t < cnt; t++) {
            int2 e0 = stg[t];
            acc0 = fmaf(__int_as_float(e0.y), tmp[e0.x * 32 + lane], acc0);
        }
        __syncwarp();
    }
    int deg = s1 - s0;
    float acc = (acc0 + acc1) + (acc2 + acc3);
    return deg > 0 ? acc * (1.0f / (float)deg) : 0.f;
}

template <int L>
__global__ void k_prop_norm(float* __restrict__ out, int toOut)
{
    __shared__ int2 stage[8][32];
    int gt = blockIdx.x * blockDim.x + threadIdx.x;
    int n = gt >> 5;
    int lane = gt & 31;
    int wid = (threadIdx.x >> 5);
    if (n >= N_NODES) return;

    float up = seg_sum<L>(g_off_up, g_eup, g_tmp_up,   n, lane, stage[wid]);
    float dn = seg_sum<L>(g_off_dn, g_edn, g_tmp_down, n, lane, stage[wid]);
    float b  = g_bias[n * 32 + lane];

    float ss = up * up + dn * dn + b * b;
#pragma unroll
    for (int o = 16; o; o >>= 1) ss += __shfl_xor_sync(0xFFFFFFFFu, ss, o);
    float inv = 1.0f / fmaxf(sqrtf(ss), 1e-12f);

    float va = up * inv; va = va >= 0.f ? va : 0.1f * va;
    float vb = dn * inv; vb = vb >= 0.f ? vb : 0.1f * vb;
    float vc = b  * inv; vc = vc >= 0.f ? vc : 0.1f * vc;

    float* dstp = toOut ? out : (float*)g_h;
    dstp[n * 96 + lane]      = va;
    dstp[n * 96 + 32 + lane] = vb;
    dstp[n * 96 + 64 + lane] = vc;
}

// ---------------- host launch ----------------
extern "C" void kernel_launch(void* const* d_in, const int* in_sizes, int n_in,
                              void* d_out, int out_size)
{
    const float* x   = (const float*)d_in[0];
    const int*   ei  = (const int*)d_in[1];
    const float* w1u = (const float*)d_in[2];
    const float* w1d = (const float*)d_in[3];
    const float* w1b = (const float*)d_in[4];
    const float* e1u = (const float*)d_in[5];
    const float* e1d = (const float*)d_in[6];
    const float* w2u = (const float*)d_in[7];
    const float* w2d = (const float*)d_in[8];
    const float* w2b = (const float*)d_in[9];
    const float* e2u = (const float*)d_in[10];
    const float* e2d = (const float*)d_in[11];
    const float* w3u = (const float*)d_in[12];
    const float* w3d = (const float*)d_in[13];
    const float* w3b = (const float*)d_in[14];
    const float* e3u = (const float*)d_in[15];
    const float* e3d = (const float*)d_in[16];
    float* out = (float*)d_out;

    const int NB_N    = (N_NODES + 255) / 256;             // 196
    const int NB_E    = N_EDGES / 256;                     // 6250
    const int NB_GEMM = (N_NODES + 127) / 128;             // 391
    const int NB_PROP = (N_NODES * 32 + 255) / 256;        // 6250
    dim3 scan_grid(NBLK_SCAN, 2);

    // ---- prep + CSR build ----
    k_zero_detect<<<NB_N, 256>>>(ei);
    k_prep<<<NB_E, 256>>>(ei);
    k_blockscan<<<scan_grid, 1024>>>();
    k_scanpart<<<1, 64>>>();
    k_addcarry<<<scan_grid, 1024>>>();
    k_fillmean<<<NB_E, 256>>>(e1u, e2u, e3u, e1d, e2d, e3d, out);

    // ---- layer 1 ----
    k_gemm<8, 12><<<NB_GEMM, 256>>>(x, 0, w1u, w1d, w1b);
    k_prop_norm<0><<<NB_PROP, 256>>>(nullptr, 0);

    // ---- layer 2 ----
    k_gemm<96, 100><<<NB_GEMM, 256>>>(nullptr, 1, w2u, w2d, w2b);
    k_prop_norm<1><<<NB_PROP, 256>>>(nullptr, 0);

    // ---- layer 3 ----
    k_gemm<96, 100><<<NB_GEMM, 256>>>(nullptr, 1, w3u, w3d, w3b);
    k_prop_norm<2><<<NB_PROP, 256>>>(out, 1);
}